// round 15
// baseline (speedup 1.0000x reference)
#include <cuda_runtime.h>
#include <cuda_bf16.h>
#include <cstdint>

#define LATDIM 128
#define HEADS 4
#define MAXN 100000
#define MAXE 600000
#define SCAN_THREADS 1024

// Scratch (allocation-free: device globals)
__device__ float g_Q[(size_t)MAXN * LATDIM];
__device__ float g_KV[(size_t)MAXN * 256];   // per node: K[0..127] then V[128..255]
__device__ float g_attNorm[(size_t)MAXN * HEADS];
__device__ int   g_count[MAXN];
__device__ int   g_offset[MAXN + 1];
__device__ int   g_cursor[MAXN];
__device__ int   g_csrRow[MAXE];
__device__ int   g_csrCol[MAXE];
// Pre-split weights, chunk-major: [w][kstep][n*8+kp], 8KB per (w,kstep) chunk
__device__ uint2 g_Bc[3][8][1024];

#define AKS 68        // A smem row stride (uint2)
#define BKS 12        // B smem row stride (uint2)
#define NSLOT 3
#define NCHUNK 24
#define GEMM_SMEM ((64 * AKS + NSLOT * 128 * BKS) * (int)sizeof(uint2))   // 71680 B

// ---------------- bf16 split helpers ----------------
__device__ __forceinline__ uint2 split2(float x0, float x1) {
    __nv_bfloat16 h0 = __float2bfloat16(x0);
    __nv_bfloat16 h1 = __float2bfloat16(x1);
    __nv_bfloat16 l0 = __float2bfloat16(x0 - __bfloat162float(h0));
    __nv_bfloat16 l1 = __float2bfloat16(x1 - __bfloat162float(h1));
    __nv_bfloat162 hh = __nv_bfloat162(h0, h1);
    __nv_bfloat162 ll = __nv_bfloat162(l0, l1);
    uint2 r;
    r.x = *reinterpret_cast<uint32_t*>(&hh);
    r.y = *reinterpret_cast<uint32_t*>(&ll);
    return r;
}

__device__ __forceinline__ void mma_bf16(float* d, const uint32_t* a,
                                         uint32_t b0, uint32_t b1) {
    asm volatile(
        "mma.sync.aligned.m16n8k16.row.col.f32.bf16.bf16.f32 "
        "{%0,%1,%2,%3}, {%4,%5,%6,%7}, {%8,%9}, {%0,%1,%2,%3};"
        : "+f"(d[0]), "+f"(d[1]), "+f"(d[2]), "+f"(d[3])
        : "r"(a[0]), "r"(a[1]), "r"(a[2]), "r"(a[3]), "r"(b0), "r"(b1));
}

// ---------------- zero kernel: out, attNorm, counts ----------------
__global__ void zero_all(float4* __restrict__ out, int n4_out, int n4_norm, int n4_cnt) {
    int i = blockIdx.x * blockDim.x + threadIdx.x;
    float4 z = make_float4(0.f, 0.f, 0.f, 0.f);
    if (i < n4_out) out[i] = z;
    if (i < n4_norm) ((float4*)g_attNorm)[i] = z;
    if (i < n4_cnt) ((int4*)g_count)[i] = make_int4(0, 0, 0, 0);
}

// ---------------- CSR build ----------------
__global__ void count_rows(const int* __restrict__ rows, int E) {
    int e = blockIdx.x * blockDim.x + threadIdx.x;
    if (e < E) atomicAdd(&g_count[__ldg(&rows[e])], 1);
}
__global__ void __launch_bounds__(SCAN_THREADS)
scan_counts(int N) {
    __shared__ int sums[SCAN_THREADS];
    int tid = threadIdx.x;
    int chunk = (N + SCAN_THREADS - 1) / SCAN_THREADS;
    int beg = tid * chunk;
    int end = min(beg + chunk, N);
    int s = 0;
    for (int i = beg; i < end; ++i) s += g_count[i];
    sums[tid] = s;
    __syncthreads();
    for (int off = 1; off < SCAN_THREADS; off <<= 1) {
        int t = (tid >= off) ? sums[tid - off] : 0;
        __syncthreads();
        sums[tid] += t;
        __syncthreads();
    }
    int run = sums[tid] - s;
    for (int i = beg; i < end; ++i) {
        int c = g_count[i];
        g_offset[i] = run;
        g_cursor[i] = run;
        run += c;
    }
    if (tid == SCAN_THREADS - 1) g_offset[N] = run;
}
__global__ void fill_csr(const int* __restrict__ rows, const int* __restrict__ cols, int E) {
    int e = blockIdx.x * blockDim.x + threadIdx.x;
    if (e < E) {
        int r = __ldg(&rows[e]);
        int pos = atomicAdd(&g_cursor[r], 1);
        g_csrRow[pos] = r;
        g_csrCol[pos] = __ldg(&cols[e]);
    }
}

// ---------------- pre-split weights, chunk-major ----------------
__global__ void presplit_b(const float* __restrict__ qT,
                           const float* __restrict__ kT,
                           const float* __restrict__ vT) {
    int t = blockIdx.x * blockDim.x + threadIdx.x;
    if (t >= 3 * 8192) return;
    int w = t / 8192;
    int i = t & 8191;
    int s = i >> 10;
    int j = i & 1023;
    int n = j >> 3;
    int kp = j & 7;
    const float* W = (w == 0) ? qT : (w == 1) ? kT : vT;
    int k0 = (s * 8 + kp) * 2;
    g_Bc[w][s][n * 8 + kp] = split2(W[k0 * 128 + n], W[(k0 + 1) * 128 + n]);
}

// ---------------- QKV GEMM: cp.async pipelined, fully unrolled (R12, proven) ----------------
__global__ void __launch_bounds__(256, 3)
qkv_gemm_mma(const float* __restrict__ embeds, int N) {
    extern __shared__ uint2 sm[];
    uint2* As = sm;
    uint2* Bb = sm + 64 * AKS;

    const int tid = threadIdx.x;
    const int wid = tid >> 5;
    const int lane = tid & 31;
    const int m0 = blockIdx.x * 64;

    const int wm = wid & 1;
    const int wn = wid >> 1;
    const int r = lane >> 2;
    const int c = lane & 3;

    const uint32_t bb_base = (uint32_t)__cvta_generic_to_shared(Bb);
    const int n1 = tid >> 2,          p1 = tid & 3;
    const int n2 = (tid + 256) >> 2,  p2 = tid & 3;
    const uint32_t d1 = (uint32_t)(n1 * BKS + p1 * 2) * 8u;
    const uint32_t d2 = (uint32_t)(n2 * BKS + p2 * 2) * 8u;
    const int s1 = n1 * 8 + p1 * 2;
    const int s2 = n2 * 8 + p2 * 2;

    for (int t = tid; t < 64 * 32; t += 256) {
        int m = t >> 5;
        int f4 = t & 31;
        float4 v = make_float4(0.f, 0.f, 0.f, 0.f);
        if (m0 + m < N) v = ((const float4*)embeds)[(size_t)(m0 + m) * 32 + f4];
        As[m * AKS + 2 * f4]     = split2(v.x, v.y);
        As[m * AKS + 2 * f4 + 1] = split2(v.z, v.w);
    }

#pragma unroll
    for (int g = 0; g < 2; ++g) {
        const uint2* src = g_Bc[0][g];
        uint32_t base = bb_base + (uint32_t)(g * 128 * BKS) * 8u;
        asm volatile("cp.async.cg.shared.global [%0], [%1], 16;"
                     :: "r"(base + d1), "l"(src + s1) : "memory");
        asm volatile("cp.async.cg.shared.global [%0], [%1], 16;"
                     :: "r"(base + d2), "l"(src + s2) : "memory");
        asm volatile("cp.async.commit_group;" ::: "memory");
    }

    float acc[2][4][4];

#pragma unroll
    for (int g = 0; g < NCHUNK; ++g) {
        const int s = g & 7;
        const int w = g >> 3;
        const int slot = g % NSLOT;

        asm volatile("cp.async.wait_group 1;" ::: "memory");
        __syncthreads();

        if (g + 2 < NCHUNK) {
            const int gn = g + 2;
            const uint2* src = g_Bc[gn >> 3][gn & 7];
            uint32_t base = bb_base + (uint32_t)((gn % NSLOT) * 128 * BKS) * 8u;
            asm volatile("cp.async.cg.shared.global [%0], [%1], 16;"
                         :: "r"(base + d1), "l"(src + s1) : "memory");
            asm volatile("cp.async.cg.shared.global [%0], [%1], 16;"
                         :: "r"(base + d2), "l"(src + s2) : "memory");
        }
        asm volatile("cp.async.commit_group;" ::: "memory");

        if (s == 0) {
#pragma unroll
            for (int mt = 0; mt < 2; ++mt)
#pragma unroll
                for (int nt = 0; nt < 4; ++nt)
#pragma unroll
                    for (int i = 0; i < 4; ++i) acc[mt][nt][i] = 0.0f;
        }

        const uint2* Bc = Bb + slot * 128 * BKS;
        const int kpA = s * 8 + c;

        uint32_t bh[4][2], bl[4][2];
#pragma unroll
        for (int nt = 0; nt < 4; ++nt) {
            const uint2* nb = Bc + (wn * 32 + nt * 8 + r) * BKS;
            uint2 q0 = nb[c];
            uint2 q1 = nb[c + 4];
            bh[nt][0] = q0.x; bh[nt][1] = q1.x;
            bl[nt][0] = q0.y; bl[nt][1] = q1.y;
        }

        uint32_t ah[2][4], al[2][4];
#pragma unroll
        for (int mt = 0; mt < 2; ++mt) {
            const uint2* base = As + (wm * 32 + mt * 16 + r) * AKS;
            uint2 p00 = base[kpA];
            uint2 p10 = base[8 * AKS + kpA];
            uint2 p01 = base[kpA + 4];
            uint2 p11 = base[8 * AKS + kpA + 4];
            ah[mt][0] = p00.x; ah[mt][1] = p10.x; ah[mt][2] = p01.x; ah[mt][3] = p11.x;
            al[mt][0] = p00.y; al[mt][1] = p10.y; al[mt][2] = p01.y; al[mt][3] = p11.y;
        }

#pragma unroll
        for (int nt = 0; nt < 4; ++nt)
#pragma unroll
            for (int mt = 0; mt < 2; ++mt)
                mma_bf16(acc[mt][nt], ah[mt], bh[nt][0], bh[nt][1]);
#pragma unroll
        for (int nt = 0; nt < 4; ++nt)
#pragma unroll
            for (int mt = 0; mt < 2; ++mt)
                mma_bf16(acc[mt][nt], ah[mt], bl[nt][0], bl[nt][1]);
#pragma unroll
        for (int nt = 0; nt < 4; ++nt)
#pragma unroll
            for (int mt = 0; mt < 2; ++mt)
                mma_bf16(acc[mt][nt], al[mt], bh[nt][0], bh[nt][1]);

        if (s == 7) {
            // D layout: Q -> g_Q[row*128]; K -> g_KV[row*256]; V -> g_KV[row*256+128]
#pragma unroll
            for (int mt = 0; mt < 2; ++mt) {
                int grow = m0 + wm * 32 + mt * 16 + r;
#pragma unroll
                for (int nt = 0; nt < 4; ++nt) {
                    int gcol = wn * 32 + nt * 8 + c * 2;
                    float* D0 = (w == 0) ? &g_Q[(size_t)grow * 128]
                              : (w == 1) ? &g_KV[(size_t)grow * 256]
                                         : &g_KV[(size_t)grow * 256 + 128];
                    float* D1 = (w == 0) ? &g_Q[(size_t)(grow + 8) * 128]
                              : (w == 1) ? &g_KV[(size_t)(grow + 8) * 256]
                                         : &g_KV[(size_t)(grow + 8) * 256 + 128];
                    if (grow < N) {
                        float2 v0 = make_float2(acc[mt][nt][0], acc[mt][nt][1]);
                        *(float2*)&D0[gcol] = v0;
                    }
                    if (grow + 8 < N) {
                        float2 v1 = make_float2(acc[mt][nt][2], acc[mt][nt][3]);
                        *(float2*)&D1[gcol] = v1;
                    }
                }
            }
        }
    }
}

// ---------------- Fused edge pass: CSR-ordered, 2 edges/warp ----------------
__global__ void __launch_bounds__(256)
edge_fused(const float* __restrict__ filt, float* __restrict__ out, int E) {
    int w = (blockIdx.x * blockDim.x + threadIdx.x) >> 5;
    int lane = threadIdx.x & 31;
    int e0 = 2 * w;
    if (e0 >= E) return;
    bool has1 = (e0 + 1 < E);
    int h = lane >> 3;

    int r0 = __ldg(&g_csrRow[e0]);
    int c0 = __ldg(&g_csrCol[e0]);
    int r1 = has1 ? __ldg(&g_csrRow[e0 + 1]) : r0;
    int c1 = has1 ? __ldg(&g_csrCol[e0 + 1]) : c0;

    float f0 = __ldg(&filt[(size_t)c0 * 4 + h]);
    float f1 = __ldg(&filt[(size_t)c1 * 4 + h]);

    float4 q0 = ((const float4*)g_Q)[(size_t)r0 * 32 + lane];
    float4 k0 = ((const float4*)g_KV)[(size_t)c0 * 64 + lane];
    float4 v0 = ((const float4*)g_KV)[(size_t)c0 * 64 + 32 + lane];
    float4 q1 = ((const float4*)g_Q)[(size_t)r1 * 32 + lane];
    float4 k1 = ((const float4*)g_KV)[(size_t)c1 * 64 + lane];
    float4 v1 = ((const float4*)g_KV)[(size_t)c1 * 64 + 32 + lane];

    float p0 = q0.x * k0.x + q0.y * k0.y + q0.z * k0.z + q0.w * k0.w;
    float p1 = q1.x * k1.x + q1.y * k1.y + q1.z * k1.z + q1.w * k1.w;
#pragma unroll
    for (int off = 4; off >= 1; off >>= 1) {
        p0 += __shfl_xor_sync(0xffffffffu, p0, off);
        p1 += __shfl_xor_sync(0xffffffffu, p1, off);
    }

    float ea0 = __expf(fminf(fmaxf(p0, -10.0f), 10.0f) + f0);
    float ea1 = __expf(fminf(fmaxf(p1, -10.0f), 10.0f) + f1);

    v0.x *= ea0; v0.y *= ea0; v0.z *= ea0; v0.w *= ea0;
    float* dst0 = out + (size_t)r0 * 128 + lane * 4;
    asm volatile("red.global.add.v4.f32 [%0], {%1, %2, %3, %4};"
                 :: "l"(dst0), "f"(v0.x), "f"(v0.y), "f"(v0.z), "f"(v0.w)
                 : "memory");
    if (has1) {
        v1.x *= ea1; v1.y *= ea1; v1.z *= ea1; v1.w *= ea1;
        float* dst1 = out + (size_t)r1 * 128 + lane * 4;
        asm volatile("red.global.add.v4.f32 [%0], {%1, %2, %3, %4};"
                     :: "l"(dst1), "f"(v1.x), "f"(v1.y), "f"(v1.z), "f"(v1.w)
                     : "memory");
    }

    if ((lane & 7) == 0) {
        atomicAdd(&g_attNorm[(size_t)r0 * 4 + h], ea0);
        if (has1) atomicAdd(&g_attNorm[(size_t)r1 * 4 + h], ea1);
    }
}

// ---------------- normalize: out[r] /= (norm[r,h] + 1e-8) ----------------
__global__ void normalize_out(float* __restrict__ out, int N) {
    int i = blockIdx.x * blockDim.x + threadIdx.x;
    if (i >= N * 32) return;
    int r = i >> 5;
    int h = (i & 31) >> 3;
    float inv = 1.0f / (__ldg(&g_attNorm[(size_t)r * 4 + h]) + 1e-8f);
    float4 v = ((float4*)out)[i];
    v.x *= inv; v.y *= inv; v.z *= inv; v.w *= inv;
    ((float4*)out)[i] = v;
}

// ---------------- launch ----------------
extern "C" void kernel_launch(void* const* d_in, const int* in_sizes, int n_in,
                              void* d_out, int out_size) {
    const float* embeds = (const float*)d_in[0];
    const float* qT = (const float*)d_in[1];
    const float* kT = (const float*)d_in[2];
    const float* vT = (const float*)d_in[3];
    const float* filt = (const float*)d_in[4];
    const int* rows = (const int*)d_in[5];
    const int* cols = (const int*)d_in[6];
    float* out = (float*)d_out;

    int N = in_sizes[0] / LATDIM;
    int E = in_sizes[5];
    int n4_out = N * 32;
    int n4_norm = N;
    int n4_cnt = (N + 3) / 4;

    cudaFuncSetAttribute(qkv_gemm_mma, cudaFuncAttributeMaxDynamicSharedMemorySize, GEMM_SMEM);

    // GEMM stays launch #4. Dependencies: zero->count->scan->fill->edge; presplit->gemm->edge.
    zero_all<<<(n4_out + 255) / 256, 256>>>((float4*)out, n4_out, n4_norm, n4_cnt);
    count_rows<<<(E + 255) / 256, 256>>>(rows, E);
    presplit_b<<<(3 * 8192 + 255) / 256, 256>>>(qT, kT, vT);
    qkv_gemm_mma<<<(N + 63) / 64, 256, GEMM_SMEM>>>(embeds, N);
    scan_counts<<<1, SCAN_THREADS>>>(N);
    fill_csr<<<(E + 255) / 256, 256>>>(rows, cols, E);

    int nWarps = (E + 1) / 2;
    int blocksE = (nWarps * 32 + 255) / 256;
    edge_fused<<<blocksE, 256>>>(filt, out, E);
    normalize_out<<<(N * 32 + 255) / 256, 256>>>(out, N);
}

// round 17
// speedup vs baseline: 1.5137x; 1.5137x over previous
#include <cuda_runtime.h>
#include <cuda_bf16.h>
#include <cstdint>

#define LATDIM 128
#define HEADS 4
#define MAXN 100000
#define MAXE 600000

// Scratch (allocation-free: device globals)
__device__ float g_Q[(size_t)MAXN * LATDIM];
__device__ float g_K[(size_t)MAXN * LATDIM];
__device__ float g_V[(size_t)MAXN * LATDIM];
__device__ float g_attNorm[(size_t)MAXN * HEADS];
// Pre-split weights, chunk-major: [w][kstep][n*8+kp], 8KB per (w,kstep) chunk
__device__ uint2 g_Bc[3][8][1024];

#define AKS 68        // A smem row stride (uint2)
#define BKS 12        // B smem row stride (uint2)
#define NSLOT 3
#define NCHUNK 24
#define GEMM_SMEM ((64 * AKS + NSLOT * 128 * BKS) * (int)sizeof(uint2))   // 71680 B

// ---------------- bf16 split helpers ----------------
__device__ __forceinline__ uint2 split2(float x0, float x1) {
    __nv_bfloat16 h0 = __float2bfloat16(x0);
    __nv_bfloat16 h1 = __float2bfloat16(x1);
    __nv_bfloat16 l0 = __float2bfloat16(x0 - __bfloat162float(h0));
    __nv_bfloat16 l1 = __float2bfloat16(x1 - __bfloat162float(h1));
    __nv_bfloat162 hh = __nv_bfloat162(h0, h1);
    __nv_bfloat162 ll = __nv_bfloat162(l0, l1);
    uint2 r;
    r.x = *reinterpret_cast<uint32_t*>(&hh);
    r.y = *reinterpret_cast<uint32_t*>(&ll);
    return r;
}

__device__ __forceinline__ void mma_bf16(float* d, const uint32_t* a,
                                         uint32_t b0, uint32_t b1) {
    asm volatile(
        "mma.sync.aligned.m16n8k16.row.col.f32.bf16.bf16.f32 "
        "{%0,%1,%2,%3}, {%4,%5,%6,%7}, {%8,%9}, {%0,%1,%2,%3};"
        : "+f"(d[0]), "+f"(d[1]), "+f"(d[2]), "+f"(d[3])
        : "r"(a[0]), "r"(a[1]), "r"(a[2]), "r"(a[3]), "r"(b0), "r"(b1));
}

// ---------------- zero attNorm only (out zeroed inside GEMM) ----------------
__global__ void zero_norm(int n4_norm) {
    int i = blockIdx.x * blockDim.x + threadIdx.x;
    if (i < n4_norm) ((float4*)g_attNorm)[i] = make_float4(0.f, 0.f, 0.f, 0.f);
}

// ---------------- pre-split weights, chunk-major ----------------
__global__ void presplit_b(const float* __restrict__ qT,
                           const float* __restrict__ kT,
                           const float* __restrict__ vT) {
    int t = blockIdx.x * blockDim.x + threadIdx.x;
    if (t >= 3 * 8192) return;
    int w = t / 8192;
    int i = t & 8191;
    int s = i >> 10;
    int j = i & 1023;
    int n = j >> 3;
    int kp = j & 7;
    const float* W = (w == 0) ? qT : (w == 1) ? kT : vT;
    int k0 = (s * 8 + kp) * 2;
    g_Bc[w][s][n * 8 + kp] = split2(W[k0 * 128 + n], W[(k0 + 1) * 128 + n]);
}

// ---------------- QKV GEMM: cp.async pipelined, fully unrolled (R12) + out-zero ----------------
__global__ void __launch_bounds__(256, 3)
qkv_gemm_mma(const float* __restrict__ embeds, float* __restrict__ out, int N) {
    extern __shared__ uint2 sm[];
    uint2* As = sm;
    uint2* Bb = sm + 64 * AKS;

    const int tid = threadIdx.x;
    const int wid = tid >> 5;
    const int lane = tid & 31;
    const int m0 = blockIdx.x * 64;

    const int wm = wid & 1;
    const int wn = wid >> 1;
    const int r = lane >> 2;
    const int c = lane & 3;

    const uint32_t bb_base = (uint32_t)__cvta_generic_to_shared(Bb);
    const int n1 = tid >> 2,          p1 = tid & 3;
    const int n2 = (tid + 256) >> 2,  p2 = tid & 3;
    const uint32_t d1 = (uint32_t)(n1 * BKS + p1 * 2) * 8u;
    const uint32_t d2 = (uint32_t)(n2 * BKS + p2 * 2) * 8u;
    const int s1 = n1 * 8 + p1 * 2;
    const int s2 = n2 * 8 + p2 * 2;

    // ---- A: load + split; also zero this block's out rows (overlapped) ----
    for (int t = tid; t < 64 * 32; t += 256) {
        int m = t >> 5;
        int f4 = t & 31;
        float4 v = make_float4(0.f, 0.f, 0.f, 0.f);
        if (m0 + m < N) {
            v = ((const float4*)embeds)[(size_t)(m0 + m) * 32 + f4];
            ((float4*)out)[(size_t)(m0 + m) * 32 + f4] = make_float4(0.f, 0.f, 0.f, 0.f);
        }
        As[m * AKS + 2 * f4]     = split2(v.x, v.y);
        As[m * AKS + 2 * f4 + 1] = split2(v.z, v.w);
    }

#pragma unroll
    for (int g = 0; g < 2; ++g) {
        const uint2* src = g_Bc[0][g];
        uint32_t base = bb_base + (uint32_t)(g * 128 * BKS) * 8u;
        asm volatile("cp.async.cg.shared.global [%0], [%1], 16;"
                     :: "r"(base + d1), "l"(src + s1) : "memory");
        asm volatile("cp.async.cg.shared.global [%0], [%1], 16;"
                     :: "r"(base + d2), "l"(src + s2) : "memory");
        asm volatile("cp.async.commit_group;" ::: "memory");
    }

    float acc[2][4][4];

#pragma unroll
    for (int g = 0; g < NCHUNK; ++g) {
        const int s = g & 7;
        const int w = g >> 3;
        const int slot = g % NSLOT;

        asm volatile("cp.async.wait_group 1;" ::: "memory");
        __syncthreads();

        if (g + 2 < NCHUNK) {
            const int gn = g + 2;
            const uint2* src = g_Bc[gn >> 3][gn & 7];
            uint32_t base = bb_base + (uint32_t)((gn % NSLOT) * 128 * BKS) * 8u;
            asm volatile("cp.async.cg.shared.global [%0], [%1], 16;"
                         :: "r"(base + d1), "l"(src + s1) : "memory");
            asm volatile("cp.async.cg.shared.global [%0], [%1], 16;"
                         :: "r"(base + d2), "l"(src + s2) : "memory");
        }
        asm volatile("cp.async.commit_group;" ::: "memory");

        if (s == 0) {
#pragma unroll
            for (int mt = 0; mt < 2; ++mt)
#pragma unroll
                for (int nt = 0; nt < 4; ++nt)
#pragma unroll
                    for (int i = 0; i < 4; ++i) acc[mt][nt][i] = 0.0f;
        }

        const uint2* Bc = Bb + slot * 128 * BKS;
        const int kpA = s * 8 + c;

        uint32_t bh[4][2], bl[4][2];
#pragma unroll
        for (int nt = 0; nt < 4; ++nt) {
            const uint2* nb = Bc + (wn * 32 + nt * 8 + r) * BKS;
            uint2 q0 = nb[c];
            uint2 q1 = nb[c + 4];
            bh[nt][0] = q0.x; bh[nt][1] = q1.x;
            bl[nt][0] = q0.y; bl[nt][1] = q1.y;
        }

        uint32_t ah[2][4], al[2][4];
#pragma unroll
        for (int mt = 0; mt < 2; ++mt) {
            const uint2* base = As + (wm * 32 + mt * 16 + r) * AKS;
            uint2 p00 = base[kpA];
            uint2 p10 = base[8 * AKS + kpA];
            uint2 p01 = base[kpA + 4];
            uint2 p11 = base[8 * AKS + kpA + 4];
            ah[mt][0] = p00.x; ah[mt][1] = p10.x; ah[mt][2] = p01.x; ah[mt][3] = p11.x;
            al[mt][0] = p00.y; al[mt][1] = p10.y; al[mt][2] = p01.y; al[mt][3] = p11.y;
        }

#pragma unroll
        for (int nt = 0; nt < 4; ++nt)
#pragma unroll
            for (int mt = 0; mt < 2; ++mt)
                mma_bf16(acc[mt][nt], ah[mt], bh[nt][0], bh[nt][1]);
#pragma unroll
        for (int nt = 0; nt < 4; ++nt)
#pragma unroll
            for (int mt = 0; mt < 2; ++mt)
                mma_bf16(acc[mt][nt], ah[mt], bl[nt][0], bl[nt][1]);
#pragma unroll
        for (int nt = 0; nt < 4; ++nt)
#pragma unroll
            for (int mt = 0; mt < 2; ++mt)
                mma_bf16(acc[mt][nt], al[mt], bh[nt][0], bh[nt][1]);

        if (s == 7) {
            float* D = (w == 0) ? g_Q : (w == 1) ? g_K : g_V;
#pragma unroll
            for (int mt = 0; mt < 2; ++mt) {
                int grow = m0 + wm * 32 + mt * 16 + r;
#pragma unroll
                for (int nt = 0; nt < 4; ++nt) {
                    int gcol = wn * 32 + nt * 8 + c * 2;
                    if (grow < N) {
                        float2 v0 = make_float2(acc[mt][nt][0], acc[mt][nt][1]);
                        *(float2*)&D[(size_t)grow * 128 + gcol] = v0;
                    }
                    if (grow + 8 < N) {
                        float2 v1 = make_float2(acc[mt][nt][2], acc[mt][nt][3]);
                        *(float2*)&D[(size_t)(grow + 8) * 128 + gcol] = v1;
                    }
                }
            }
        }
    }
}

// ---------------- Fused edge pass: 2 edges/warp, L2-resident scatter ----------------
__global__ void __launch_bounds__(256)
edge_fused(const int* __restrict__ rows, const int* __restrict__ cols,
           const float* __restrict__ filt, float* __restrict__ out, int E) {
    int w = (blockIdx.x * blockDim.x + threadIdx.x) >> 5;
    int lane = threadIdx.x & 31;
    int e0 = 2 * w;
    if (e0 >= E) return;
    bool has1 = (e0 + 1 < E);
    int h = lane >> 3;

    // L2 evict-last policy for out / attNorm (small, heavily re-touched)
    unsigned long long pol;
    asm("createpolicy.fractional.L2::evict_last.b64 %0, 1.0;" : "=l"(pol));

    int r0 = __ldg(&rows[e0]);
    int c0 = __ldg(&cols[e0]);
    int r1 = has1 ? __ldg(&rows[e0 + 1]) : r0;
    int c1 = has1 ? __ldg(&cols[e0 + 1]) : c0;

    float f0 = __ldg(&filt[(size_t)c0 * 4 + h]);
    float f1 = __ldg(&filt[(size_t)c1 * 4 + h]);

    float4 q0 = ((const float4*)g_Q)[(size_t)r0 * 32 + lane];
    float4 k0 = ((const float4*)g_K)[(size_t)c0 * 32 + lane];
    float4 v0 = ((const float4*)g_V)[(size_t)c0 * 32 + lane];
    float4 q1 = ((const float4*)g_Q)[(size_t)r1 * 32 + lane];
    float4 k1 = ((const float4*)g_K)[(size_t)c1 * 32 + lane];
    float4 v1 = ((const float4*)g_V)[(size_t)c1 * 32 + lane];

    float p0 = q0.x * k0.x + q0.y * k0.y + q0.z * k0.z + q0.w * k0.w;
    float p1 = q1.x * k1.x + q1.y * k1.y + q1.z * k1.z + q1.w * k1.w;
#pragma unroll
    for (int off = 4; off >= 1; off >>= 1) {
        p0 += __shfl_xor_sync(0xffffffffu, p0, off);
        p1 += __shfl_xor_sync(0xffffffffu, p1, off);
    }

    float ea0 = __expf(fminf(fmaxf(p0, -10.0f), 10.0f) + f0);
    float ea1 = __expf(fminf(fmaxf(p1, -10.0f), 10.0f) + f1);

    v0.x *= ea0; v0.y *= ea0; v0.z *= ea0; v0.w *= ea0;
    float* dst0 = out + (size_t)r0 * 128 + lane * 4;
    asm volatile("red.global.L2::cache_hint.add.v4.f32 [%0], {%1, %2, %3, %4}, %5;"
                 :: "l"(dst0), "f"(v0.x), "f"(v0.y), "f"(v0.z), "f"(v0.w), "l"(pol)
                 : "memory");
    if (has1) {
        v1.x *= ea1; v1.y *= ea1; v1.z *= ea1; v1.w *= ea1;
        float* dst1 = out + (size_t)r1 * 128 + lane * 4;
        asm volatile("red.global.L2::cache_hint.add.v4.f32 [%0], {%1, %2, %3, %4}, %5;"
                     :: "l"(dst1), "f"(v1.x), "f"(v1.y), "f"(v1.z), "f"(v1.w), "l"(pol)
                     : "memory");
    }

    if ((lane & 7) == 0) {
        asm volatile("red.global.L2::cache_hint.add.f32 [%0], %1, %2;"
                     :: "l"(&g_attNorm[(size_t)r0 * 4 + h]), "f"(ea0), "l"(pol) : "memory");
        if (has1)
            asm volatile("red.global.L2::cache_hint.add.f32 [%0], %1, %2;"
                         :: "l"(&g_attNorm[(size_t)r1 * 4 + h]), "f"(ea1), "l"(pol) : "memory");
    }
}

// ---------------- normalize: out[r] /= (norm[r,h] + 1e-8) ----------------
__global__ void normalize_out(float* __restrict__ out, int N) {
    int i = blockIdx.x * blockDim.x + threadIdx.x;
    if (i >= N * 32) return;
    int r = i >> 5;
    int h = (i & 31) >> 3;
    float inv = 1.0f / (__ldg(&g_attNorm[(size_t)r * 4 + h]) + 1e-8f);
    float4 v = ((float4*)out)[i];
    v.x *= inv; v.y *= inv; v.z *= inv; v.w *= inv;
    ((float4*)out)[i] = v;
}

// ---------------- launch ----------------
extern "C" void kernel_launch(void* const* d_in, const int* in_sizes, int n_in,
                              void* d_out, int out_size) {
    const float* embeds = (const float*)d_in[0];
    const float* qT = (const float*)d_in[1];
    const float* kT = (const float*)d_in[2];
    const float* vT = (const float*)d_in[3];
    const float* filt = (const float*)d_in[4];
    const int* rows = (const int*)d_in[5];
    const int* cols = (const int*)d_in[6];
    float* out = (float*)d_out;

    int N = in_sizes[0] / LATDIM;
    int E = in_sizes[5];
    int n4_norm = N;   // attNorm float4 count

    cudaFuncSetAttribute(qkv_gemm_mma, cudaFuncAttributeMaxDynamicSharedMemorySize, GEMM_SMEM);

    // edge_fused is launch #4 (profiled) to verify the DRAM-traffic theory.
    zero_norm<<<(n4_norm + 255) / 256, 256>>>(n4_norm);
    presplit_b<<<(3 * 8192 + 255) / 256, 256>>>(qT, kT, vT);
    qkv_gemm_mma<<<(N + 63) / 64, 256, GEMM_SMEM>>>(embeds, out, N);

    int nWarps = (E + 1) / 2;
    int blocksE = (nWarps * 32 + 255) / 256;
    edge_fused<<<blocksE, 256>>>(rows, cols, filt, out, E);
    normalize_out<<<(N * 32 + 255) / 256, 256>>>(out, N);
}